// round 9
// baseline (speedup 1.0000x reference)
#include <cuda_runtime.h>
#include <cuda_fp16.h>
#include <math.h>
#include <stdint.h>

#define Bb  8
#define Cc  256
#define P1c 2048
#define P2c 4096
#define CQc 32

// Scratch (device globals: no allocation allowed in kernel_launch)
__device__ float  g_q [(size_t)Bb * P1c * CQc];   // [B, P1, 32]        2 MB
__device__ float  g_k [(size_t)Bb * CQc * P2c];   // [B, 32, P2]        4 MB
__device__ __half g_vh[(size_t)Bb * Cc * P1c];    // v fp16 [B, C, P1]  8 MB
__device__ float  g_E [(size_t)Bb * P1c * P2c];   // exp(e) fp32 [B, p, q2] 268 MB
__device__ __half g_W [(size_t)Bb * P1c * P2c];   // normalized weights fp16 134 MB
__device__ float  g_iz[Bb * P1c];                 // 1 / row sumexp

__device__ __forceinline__ uint32_t su(const void* p) {
    return (uint32_t)__cvta_generic_to_shared(p);
}

// ---------------------------------------------------------------------------
// K1a: pointwise conv, fp32 out (q transposed, k plain)
// ---------------------------------------------------------------------------
__global__ void __launch_bounds__(256) conv1x1_kernel(
    const float* __restrict__ W, const float* __restrict__ bias,
    const float* __restrict__ x, float* __restrict__ out,
    int P, int Cout, int transpose_out)
{
    __shared__ __align__(16) float sW[Cc * 32];   // [c][o]
    const int ochunk = blockIdx.y * 32;
    const int b = blockIdx.z;
    for (int i = threadIdx.x; i < Cc * 32; i += 256) {
        int o = i & 31, c = i >> 5;
        sW[i] = W[(size_t)(ochunk + o) * Cc + c];
    }
    __syncthreads();

    const int p = blockIdx.x * 256 + threadIdx.x;
    const float* xp = x + (size_t)b * Cc * P + p;

    float acc[32];
    #pragma unroll
    for (int o = 0; o < 32; o++) acc[o] = bias[ochunk + o];

    for (int c = 0; c < Cc; c++) {
        float xv = __ldg(xp + (size_t)c * P);
        const float4* w4 = (const float4*)(sW + c * 32);
        #pragma unroll
        for (int j = 0; j < 8; j++) {
            float4 w = w4[j];
            acc[4*j+0] = fmaf(w.x, xv, acc[4*j+0]);
            acc[4*j+1] = fmaf(w.y, xv, acc[4*j+1]);
            acc[4*j+2] = fmaf(w.z, xv, acc[4*j+2]);
            acc[4*j+3] = fmaf(w.w, xv, acc[4*j+3]);
        }
    }

    if (transpose_out) {
        float* op = out + ((size_t)b * P + p) * Cout + ochunk;
        #pragma unroll
        for (int o = 0; o < 32; o++) op[o] = acc[o];
    } else {
        float* op = out + ((size_t)b * Cout + ochunk) * P + p;
        #pragma unroll
        for (int o = 0; o < 32; o++) op[(size_t)o * P] = acc[o];
    }
}

// ---------------------------------------------------------------------------
// K1b: pointwise conv, fp16 out (v)
// ---------------------------------------------------------------------------
__global__ void __launch_bounds__(256) conv1x1_h_kernel(
    const float* __restrict__ W, const float* __restrict__ bias,
    const float* __restrict__ x, __half* __restrict__ out, int P)
{
    __shared__ __align__(16) float sW[Cc * 32];
    const int ochunk = blockIdx.y * 32;
    const int b = blockIdx.z;
    for (int i = threadIdx.x; i < Cc * 32; i += 256) {
        int o = i & 31, c = i >> 5;
        sW[i] = W[(size_t)(ochunk + o) * Cc + c];
    }
    __syncthreads();

    const int p = blockIdx.x * 256 + threadIdx.x;
    const float* xp = x + (size_t)b * Cc * P + p;

    float acc[32];
    #pragma unroll
    for (int o = 0; o < 32; o++) acc[o] = bias[ochunk + o];

    for (int c = 0; c < Cc; c++) {
        float xv = __ldg(xp + (size_t)c * P);
        const float4* w4 = (const float4*)(sW + c * 32);
        #pragma unroll
        for (int j = 0; j < 8; j++) {
            float4 w = w4[j];
            acc[4*j+0] = fmaf(w.x, xv, acc[4*j+0]);
            acc[4*j+1] = fmaf(w.y, xv, acc[4*j+1]);
            acc[4*j+2] = fmaf(w.z, xv, acc[4*j+2]);
            acc[4*j+3] = fmaf(w.w, xv, acc[4*j+3]);
        }
    }

    __half* op = out + ((size_t)b * Cc + ochunk) * P + p;
    #pragma unroll
    for (int o = 0; o < 32; o++) op[(size_t)o * P] = __float2half_rn(acc[o]);
}

// ---------------------------------------------------------------------------
// K2: e[p,q2] = q[p,:]·k[:,q2]; store exp(e) (fits fp32: |e|<~40); iz[p]=1/sum.
// ---------------------------------------------------------------------------
#define TPr 16
__global__ void __launch_bounds__(256) energy_kernel()
{
    const int b  = blockIdx.y;
    const int p0 = blockIdx.x * TPr;

    __shared__ __align__(16) float sq[TPr][CQc];
    for (int i = threadIdx.x; i < TPr * CQc; i += 256) {
        int pl = i >> 5, o = i & 31;
        sq[pl][o] = g_q[((size_t)b * P1c + p0 + pl) * CQc + o];
    }
    __syncthreads();

    float s[TPr];
    #pragma unroll
    for (int i = 0; i < TPr; i++) s[i] = 0.f;

    const float* kb = g_k + (size_t)b * CQc * P2c;
    float* Eb = g_E + (size_t)b * P1c * P2c;

    for (int q2 = threadIdx.x; q2 < P2c; q2 += 256) {
        float kr[CQc];
        #pragma unroll
        for (int o = 0; o < CQc; o++) kr[o] = __ldg(kb + (size_t)o * P2c + q2);

        #pragma unroll
        for (int pl = 0; pl < TPr; pl++) {
            const float4* q4 = (const float4*)sq[pl];
            float e = 0.f;
            #pragma unroll
            for (int o4 = 0; o4 < CQc / 4; o4++) {
                float4 qv = q4[o4];
                e = fmaf(qv.x, kr[4*o4+0], e);
                e = fmaf(qv.y, kr[4*o4+1], e);
                e = fmaf(qv.z, kr[4*o4+2], e);
                e = fmaf(qv.w, kr[4*o4+3], e);
            }
            float ex = __expf(e);
            Eb[(size_t)(p0 + pl) * P2c + q2] = ex;
            s[pl] += ex;
        }
    }

    #pragma unroll
    for (int pl = 0; pl < TPr; pl++) {
        float ss = s[pl];
        #pragma unroll
        for (int off = 16; off > 0; off >>= 1)
            ss += __shfl_xor_sync(0xffffffffu, ss, off);
        s[pl] = ss;
    }

    __shared__ float rs[TPr][8];
    const int warp = threadIdx.x >> 5, lane = threadIdx.x & 31;
    if (lane == 0) {
        #pragma unroll
        for (int pl = 0; pl < TPr; pl++) rs[pl][warp] = s[pl];
    }
    __syncthreads();
    if (threadIdx.x < TPr) {
        int pl = threadIdx.x;
        float ss = 0.f;
        #pragma unroll
        for (int w = 0; w < 8; w++) ss += rs[pl][w];
        g_iz[b * P1c + p0 + pl] = 1.0f / ss;
    }
}

// ---------------------------------------------------------------------------
// W3: W[b][p][q2] = fp16( exp(e)[b][p][q2] * iz[b][p] ).  Streaming pass.
// Row index r = b*P1c + p == i >> 12 (since P2c = 4096 and 8 | 4096).
// ---------------------------------------------------------------------------
__global__ void __launch_bounds__(256) norm_kernel()
{
    const size_t i = (((size_t)blockIdx.x * 256) + threadIdx.x) * 8;
    const float iz = g_iz[i >> 12];
    float4 a = *(const float4*)(g_E + i);
    float4 c = *(const float4*)(g_E + i + 4);
    __half2 h0 = __floats2half2_rn(a.x * iz, a.y * iz);
    __half2 h1 = __floats2half2_rn(a.z * iz, a.w * iz);
    __half2 h2 = __floats2half2_rn(c.x * iz, c.y * iz);
    __half2 h3 = __floats2half2_rn(c.z * iz, c.w * iz);
    uint4 u;
    u.x = *(uint32_t*)&h0; u.y = *(uint32_t*)&h1;
    u.z = *(uint32_t*)&h2; u.w = *(uint32_t*)&h3;
    *(uint4*)(g_W + i) = u;
}

// ---------------------------------------------------------------------------
// K3: fp16 mma.sync m16n8k16 GEMM, 4-stage cp.async pipeline.
// out[c,q2] = alpha * sum_p v[c,p] * W[p,q2] + x2[c,q2]
// CTA tile 128x128, BK=32. Stage = 8KB A + 8KB B, raw 16B LDGSTS copies into
// the verified swizzled layouts; one __syncthreads per chunk; 3 chunks in
// flight. ldsm/mma compute core identical to the passing round-8 kernel.
// ---------------------------------------------------------------------------
#define BK3 32
#define NCH (P1c / BK3)
#define NST 4
#define STAGE_BYTES 16384

__device__ __forceinline__ void cp16(uint32_t dst, const void* src) {
    asm volatile("cp.async.cg.shared.global [%0], [%1], 16;"
                 :: "r"(dst), "l"(src) : "memory");
}
__device__ __forceinline__ void cp_commit() {
    asm volatile("cp.async.commit_group;" ::: "memory");
}
__device__ __forceinline__ void cp_wait2() {
    asm volatile("cp.async.wait_group 2;" ::: "memory");
}

__device__ __forceinline__ void ldsm_x4(uint32_t* r, uint32_t addr) {
    asm volatile("ldmatrix.sync.aligned.m8n8.x4.shared.b16 {%0,%1,%2,%3}, [%4];"
        : "=r"(r[0]), "=r"(r[1]), "=r"(r[2]), "=r"(r[3]) : "r"(addr));
}
__device__ __forceinline__ void ldsm_x4_t(uint32_t* r, uint32_t addr) {
    asm volatile("ldmatrix.sync.aligned.m8n8.x4.trans.shared.b16 {%0,%1,%2,%3}, [%4];"
        : "=r"(r[0]), "=r"(r[1]), "=r"(r[2]), "=r"(r[3]) : "r"(addr));
}
__device__ __forceinline__ void mma16816(float* c, const uint32_t* a,
                                         uint32_t b0, uint32_t b1) {
    asm volatile(
        "mma.sync.aligned.m16n8k16.row.col.f32.f16.f16.f32 "
        "{%0,%1,%2,%3}, {%4,%5,%6,%7}, {%8,%9}, {%0,%1,%2,%3};"
        : "+f"(c[0]), "+f"(c[1]), "+f"(c[2]), "+f"(c[3])
        : "r"(a[0]), "r"(a[1]), "r"(a[2]), "r"(a[3]), "r"(b0), "r"(b1));
}

__global__ void __launch_bounds__(256, 2) out_gemm_h(
    const float* __restrict__ x2, const float* __restrict__ alpha,
    float* __restrict__ out)
{
    extern __shared__ __align__(16) uint8_t smem[];   // NST * 16KB

    const int b  = blockIdx.z;
    const int m0 = blockIdx.y * 128;
    const int n0 = blockIdx.x * 128;
    const int tid  = threadIdx.x;
    const int wid  = tid >> 5;
    const int lane = tid & 31;
    const int wm = (wid >> 1) * 32;   // 0,32,64,96
    const int wn = (wid & 1) * 64;    // 0,64

    const __half* Abase = g_vh + ((size_t)b * Cc  + m0) * (size_t)P1c;
    const __half* Wb    = g_W  + (size_t)b * P1c * P2c + n0;

    // staging indices
    // A: 512 16B chunks/stage: row = tid>>2 (+64), c16 = tid&3
    // B: 512 16B chunks/stage: kkt = tid>>4 (+16),  nch = tid&15
    const int aRow0 = tid >> 2, aC16 = tid & 3;
    const int aS = aC16 >> 1, aC = aC16 & 1;
    const int bKt0 = tid >> 4, bNch = tid & 15;

    float acc[2][8][4];
    #pragma unroll
    for (int mt = 0; mt < 2; mt++)
        #pragma unroll
        for (int nt = 0; nt < 8; nt++)
            #pragma unroll
            for (int j = 0; j < 4; j++) acc[mt][nt][j] = 0.f;

    // ---- async stage issue: raw 16B copies into swizzled layout ----
    auto issue = [&](int ch) {
        uint8_t* st = smem + (ch & (NST - 1)) * STAGE_BYTES;
        const int k0 = ch * BK3;
        #pragma unroll
        for (int j = 0; j < 2; j++) {
            const int row = aRow0 + j * 64;
            cp16(su(st + aS * 4096 + row * 32 + ((aC ^ ((row >> 2) & 1)) << 4)),
                 Abase + (size_t)row * P1c + k0 + aC16 * 8);
        }
        #pragma unroll
        for (int j = 0; j < 2; j++) {
            const int kkt = bKt0 + j * 16;
            const int s = kkt >> 4, kk = kkt & 15;
            cp16(su(st + 8192 + s * 4096 + kk * 256 + ((bNch ^ (kk & 7)) << 4)),
                 Wb + (size_t)(k0 + kkt) * P2c + bNch * 8);
        }
    };

    // prologue: fill 3 stages
    #pragma unroll
    for (int c = 0; c < NST - 1; c++) {
        issue(c);
        cp_commit();
    }

    for (int ch = 0; ch < NCH; ch++) {
        cp_wait2();          // oldest in-flight group (== ch) complete
        __syncthreads();

        // ---- compute on stage ch%4 ----
        const uint8_t* base = smem + (ch & (NST - 1)) * STAGE_BYTES;
        #pragma unroll
        for (int s = 0; s < 2; s++) {
            uint32_t a[2][4];
            #pragma unroll
            for (int mt = 0; mt < 2; mt++) {
                const int mr = wm + mt * 16 + (lane & 7) + ((lane >> 3) & 1) * 8;
                const int clog = (lane >> 4) & 1;
                ldsm_x4(a[mt], su(base + s * 4096 + mr * 32 +
                                  ((clog ^ ((mr >> 2) & 1)) << 4)));
            }
            const int kk = (lane & 7) + ((lane >> 3) & 1) * 8;
            #pragma unroll
            for (int np = 0; np < 4; np++) {
                const int nch = (wn + np * 16 + ((lane >> 4) & 1) * 8) >> 3;
                uint32_t br[4];
                ldsm_x4_t(br, su(base + 8192 + s * 4096 + kk * 256 +
                                 ((nch ^ (kk & 7)) << 4)));
                mma16816(acc[0][np * 2],     a[0], br[0], br[1]);
                mma16816(acc[1][np * 2],     a[1], br[0], br[1]);
                mma16816(acc[0][np * 2 + 1], a[0], br[2], br[3]);
                mma16816(acc[1][np * 2 + 1], a[1], br[2], br[3]);
            }
        }

        // ---- issue chunk ch+3 into the stage freed by compute(ch-1) ----
        if (ch + NST - 1 < NCH) issue(ch + NST - 1);
        cp_commit();   // empty groups at the tail keep wait accounting aligned
    }

    // ---- epilogue: alpha * acc + x2 ----
    const float al = __ldg(alpha);
    const int g  = lane >> 2;
    const int t4 = lane & 3;
    #pragma unroll
    for (int mt = 0; mt < 2; mt++) {
        #pragma unroll
        for (int nt = 0; nt < 8; nt++) {
            const int r0 = m0 + wm + mt * 16 + g;
            const int c0 = n0 + wn + nt * 8 + 2 * t4;
            const size_t o0 = ((size_t)b * Cc + r0) * P2c + c0;
            const size_t o1 = o0 + (size_t)8 * P2c;
            float2 x0 = *(const float2*)(x2 + o0);
            float2 x1 = *(const float2*)(x2 + o1);
            float2 w0, w1;
            w0.x = fmaf(al, acc[mt][nt][0], x0.x);
            w0.y = fmaf(al, acc[mt][nt][1], x0.y);
            w1.x = fmaf(al, acc[mt][nt][2], x1.x);
            w1.y = fmaf(al, acc[mt][nt][3], x1.y);
            *(float2*)(out + o0) = w0;
            *(float2*)(out + o1) = w1;
        }
    }
}

// ---------------------------------------------------------------------------
extern "C" void kernel_launch(void* const* d_in, const int* in_sizes, int n_in,
                              void* d_out, int out_size)
{
    (void)in_sizes; (void)n_in; (void)out_size;
    const float* x1    = (const float*)d_in[0];
    const float* x2    = (const float*)d_in[1];
    const float* Wq    = (const float*)d_in[2];
    const float* bq    = (const float*)d_in[3];
    const float* Wk    = (const float*)d_in[4];
    const float* bk    = (const float*)d_in[5];
    const float* Wv    = (const float*)d_in[6];
    const float* bv    = (const float*)d_in[7];
    const float* alpha = (const float*)d_in[8];
    float* out = (float*)d_out;

    void *pq = nullptr, *pk = nullptr, *pv = nullptr;
    cudaGetSymbolAddress(&pq, g_q);
    cudaGetSymbolAddress(&pk, g_k);
    cudaGetSymbolAddress(&pv, g_vh);

    cudaFuncSetAttribute(out_gemm_h,
                         cudaFuncAttributeMaxDynamicSharedMemorySize,
                         NST * STAGE_BYTES);

    conv1x1_kernel<<<dim3(P1c / 256, 1, Bb), 256>>>(Wq, bq, x1, (float*)pq, P1c, CQc, 1);
    conv1x1_kernel<<<dim3(P2c / 256, 1, Bb), 256>>>(Wk, bk, x2, (float*)pk, P2c, CQc, 0);
    conv1x1_h_kernel<<<dim3(P1c / 256, Cc / 32, Bb), 256>>>(Wv, bv, x1, (__half*)pv, P1c);

    energy_kernel<<<dim3(P1c / TPr, Bb), 256>>>();

    norm_kernel<<<((size_t)Bb * P1c * P2c) / (256 * 8), 256>>>();

    out_gemm_h<<<dim3(P2c / 128, Cc / 128, Bb), 256, NST * STAGE_BYTES>>>(x2, alpha, out);
}

// round 10
// speedup vs baseline: 1.2820x; 1.2820x over previous
#include <cuda_runtime.h>
#include <cuda_fp16.h>
#include <math.h>
#include <stdint.h>

#define Bb  8
#define Cc  256
#define P1c 2048
#define P2c 4096
#define CQc 32

// Scratch (device globals: no allocation allowed in kernel_launch)
__device__ __half g_qh[(size_t)Bb * P1c * CQc];   // q hi fp16 [B,P1,32]  1 MB
__device__ __half g_ql[(size_t)Bb * P1c * CQc];   // q lo fp16            1 MB
__device__ __half g_kh[(size_t)Bb * CQc * P2c];   // k hi fp16 [B,32,P2]  2 MB
__device__ __half g_kl[(size_t)Bb * CQc * P2c];   // k lo fp16            2 MB
__device__ __half g_vh[(size_t)Bb * Cc * P1c];    // v fp16 [B,C,P1]      8 MB
__device__ float  g_E [(size_t)Bb * P1c * P2c];   // raw e fp32 [B,p,q2] 268 MB
__device__ __half g_W [(size_t)Bb * P1c * P2c];   // exp(e)*iz fp16      134 MB
__device__ float  g_part[(size_t)Bb * P1c * 16];  // per-block exp sums    1 MB
__device__ float  g_iz[Bb * P1c];                 // 1 / row sumexp

__device__ __forceinline__ uint32_t su(const void* p) {
    return (uint32_t)__cvta_generic_to_shared(p);
}

// ---------------------------------------------------------------------------
// K1 convs. q/k emit split fp16 (hi + lo); v emits plain fp16.
// ---------------------------------------------------------------------------
__global__ void __launch_bounds__(256) conv_qk_split_kernel(
    const float* __restrict__ W, const float* __restrict__ bias,
    const float* __restrict__ x, __half* __restrict__ oh, __half* __restrict__ ol,
    int P, int transpose_out)
{
    __shared__ __align__(16) float sW[Cc * 32];   // [c][o]
    const int b = blockIdx.z;
    for (int i = threadIdx.x; i < Cc * 32; i += 256) {
        int o = i & 31, c = i >> 5;
        sW[i] = W[(size_t)o * Cc + c];
    }
    __syncthreads();

    const int p = blockIdx.x * 256 + threadIdx.x;
    const float* xp = x + (size_t)b * Cc * P + p;

    float acc[32];
    #pragma unroll
    for (int o = 0; o < 32; o++) acc[o] = bias[o];

    for (int c = 0; c < Cc; c++) {
        float xv = __ldg(xp + (size_t)c * P);
        const float4* w4 = (const float4*)(sW + c * 32);
        #pragma unroll
        for (int j = 0; j < 8; j++) {
            float4 w = w4[j];
            acc[4*j+0] = fmaf(w.x, xv, acc[4*j+0]);
            acc[4*j+1] = fmaf(w.y, xv, acc[4*j+1]);
            acc[4*j+2] = fmaf(w.z, xv, acc[4*j+2]);
            acc[4*j+3] = fmaf(w.w, xv, acc[4*j+3]);
        }
    }

    if (transpose_out) {
        // q layout: [B, P, 32]
        const size_t base = ((size_t)b * P + p) * 32;
        #pragma unroll
        for (int o = 0; o < 32; o++) {
            __half h = __float2half_rn(acc[o]);
            oh[base + o] = h;
            ol[base + o] = __float2half_rn(acc[o] - __half2float(h));
        }
    } else {
        // k layout: [B, 32, P]
        const size_t base = (size_t)b * 32 * P + p;
        #pragma unroll
        for (int o = 0; o < 32; o++) {
            __half h = __float2half_rn(acc[o]);
            oh[base + (size_t)o * P] = h;
            ol[base + (size_t)o * P] = __float2half_rn(acc[o] - __half2float(h));
        }
    }
}

__global__ void __launch_bounds__(256) conv1x1_h_kernel(
    const float* __restrict__ W, const float* __restrict__ bias,
    const float* __restrict__ x, __half* __restrict__ out, int P)
{
    __shared__ __align__(16) float sW[Cc * 32];
    const int ochunk = blockIdx.y * 32;
    const int b = blockIdx.z;
    for (int i = threadIdx.x; i < Cc * 32; i += 256) {
        int o = i & 31, c = i >> 5;
        sW[i] = W[(size_t)(ochunk + o) * Cc + c];
    }
    __syncthreads();

    const int p = blockIdx.x * 256 + threadIdx.x;
    const float* xp = x + (size_t)b * Cc * P + p;

    float acc[32];
    #pragma unroll
    for (int o = 0; o < 32; o++) acc[o] = bias[ochunk + o];

    for (int c = 0; c < Cc; c++) {
        float xv = __ldg(xp + (size_t)c * P);
        const float4* w4 = (const float4*)(sW + c * 32);
        #pragma unroll
        for (int j = 0; j < 8; j++) {
            float4 w = w4[j];
            acc[4*j+0] = fmaf(w.x, xv, acc[4*j+0]);
            acc[4*j+1] = fmaf(w.y, xv, acc[4*j+1]);
            acc[4*j+2] = fmaf(w.z, xv, acc[4*j+2]);
            acc[4*j+3] = fmaf(w.w, xv, acc[4*j+3]);
        }
    }

    __half* op = out + ((size_t)b * Cc + ochunk) * P + p;
    #pragma unroll
    for (int o = 0; o < 32; o++) op[(size_t)o * P] = __float2half_rn(acc[o]);
}

// ---------------------------------------------------------------------------
// shared mma helpers
// ---------------------------------------------------------------------------
__device__ __forceinline__ void ldsm_x4(uint32_t* r, uint32_t addr) {
    asm volatile("ldmatrix.sync.aligned.m8n8.x4.shared.b16 {%0,%1,%2,%3}, [%4];"
        : "=r"(r[0]), "=r"(r[1]), "=r"(r[2]), "=r"(r[3]) : "r"(addr));
}
__device__ __forceinline__ void ldsm_x4_t(uint32_t* r, uint32_t addr) {
    asm volatile("ldmatrix.sync.aligned.m8n8.x4.trans.shared.b16 {%0,%1,%2,%3}, [%4];"
        : "=r"(r[0]), "=r"(r[1]), "=r"(r[2]), "=r"(r[3]) : "r"(addr));
}
__device__ __forceinline__ void mma16816(float* c, const uint32_t* a,
                                         uint32_t b0, uint32_t b1) {
    asm volatile(
        "mma.sync.aligned.m16n8k16.row.col.f32.f16.f16.f32 "
        "{%0,%1,%2,%3}, {%4,%5,%6,%7}, {%8,%9}, {%0,%1,%2,%3};"
        : "+f"(c[0]), "+f"(c[1]), "+f"(c[2]), "+f"(c[3])
        : "r"(a[0]), "r"(a[1]), "r"(a[2]), "r"(a[3]), "r"(b0), "r"(b1));
}

// ---------------------------------------------------------------------------
// K2a: tensor-core energy GEMM. Tile 64p x 256q2, K=32 single shot.
// e = qhi*khi + qhi*klo + qlo*khi (split fp16 -> fp32-accurate energies).
// Writes raw e fp32 to g_E and deterministic per-(row, q2-block) exp-sums
// to g_part (block exclusively owns its slot; no atomics).
// smem A: [64 rows][4 x 16B chunks], chunk' = c ^ ((row>>1)&3) (bank-bijective)
// smem B: [32 rows][32 x 16B chunks], chunk' = c ^ (row&7)
// ---------------------------------------------------------------------------
__global__ void __launch_bounds__(256) energy_mma_kernel()
{
    __shared__ __align__(16) uint8_t sqh[4096], sql[4096];    // 64x32 fp16
    __shared__ __align__(16) uint8_t skh[16384], skl[16384];  // 32x256 fp16
    __shared__ float s_sum[64];

    const int b  = blockIdx.z;
    const int p0 = blockIdx.y * 64;
    const int n0 = blockIdx.x * 256;
    const int tid  = threadIdx.x;
    const int wid  = tid >> 5;
    const int lane = tid & 31;
    const int wm  = (wid & 1) * 32;    // warp m offset: 0/32
    const int wnn = (wid >> 1) * 64;   // warp n offset: 0/64/128/192
    const int g  = lane >> 2;
    const int t4 = lane & 3;

    if (tid < 64) s_sum[tid] = 0.f;

    // ---- stage q tiles (hi/lo): thread -> (row = tid>>2, chunk = tid&3) ----
    {
        const int row = tid >> 2, c = tid & 3;
        const size_t src = ((size_t)b * P1c + p0 + row) * CQc + c * 8;
        const int dst = row * 64 + ((c ^ ((row >> 1) & 3)) << 4);
        *(uint4*)&sqh[dst] = *(const uint4*)(g_qh + src);
        *(uint4*)&sql[dst] = *(const uint4*)(g_ql + src);
    }
    // ---- stage k tiles (hi/lo): 1024 chunks, 4 per thread ----
    #pragma unroll
    for (int j = 0; j < 4; j++) {
        const int idx = j * 256 + tid;
        const int kr = idx >> 5, nc = idx & 31;
        const size_t src = ((size_t)b * CQc + kr) * P2c + n0 + nc * 8;
        const int dst = kr * 512 + ((nc ^ (kr & 7)) << 4);
        *(uint4*)&skh[dst] = *(const uint4*)(g_kh + src);
        *(uint4*)&skl[dst] = *(const uint4*)(g_kl + src);
    }
    __syncthreads();

    float acc[2][8][4];
    #pragma unroll
    for (int mt = 0; mt < 2; mt++)
        #pragma unroll
        for (int nt = 0; nt < 8; nt++)
            #pragma unroll
            for (int j = 0; j < 4; j++) acc[mt][nt][j] = 0.f;

    #pragma unroll
    for (int ks = 0; ks < 2; ks++) {
        // A fragments (hi & lo) for both m-tiles
        uint32_t ah[2][4], al[2][4];
        const int mr = wm + (lane & 15);
        const int kc = ks * 2 + ((lane >> 4) & 1);
        #pragma unroll
        for (int mt = 0; mt < 2; mt++) {
            const int r = mr + mt * 16;
            const int off = r * 64 + ((kc ^ ((r >> 1) & 3)) << 4);
            ldsm_x4(ah[mt], su(sqh + off));
            ldsm_x4(al[mt], su(sql + off));
        }
        const int kk = ks * 16 + (lane & 7) + ((lane >> 3) & 1) * 8;
        #pragma unroll
        for (int np = 0; np < 4; np++) {
            const int nch = (wnn + np * 16 + ((lane >> 4) & 1) * 8) >> 3;
            const int boff = kk * 512 + ((nch ^ (kk & 7)) << 4);
            uint32_t bh[4], bl[4];
            ldsm_x4_t(bh, su(skh + boff));
            ldsm_x4_t(bl, su(skl + boff));
            #pragma unroll
            for (int mt = 0; mt < 2; mt++) {
                #pragma unroll
                for (int h = 0; h < 2; h++) {
                    float* a4 = acc[mt][np * 2 + h];
                    mma16816(a4, ah[mt], bh[h*2], bh[h*2+1]);   // qhi*khi
                    mma16816(a4, ah[mt], bl[h*2], bl[h*2+1]);   // qhi*klo
                    mma16816(a4, al[mt], bh[h*2], bh[h*2+1]);   // qlo*khi
                }
            }
        }
    }

    // ---- epilogue: write raw e fp32, accumulate exp sums per row ----
    float srow[4] = {0.f, 0.f, 0.f, 0.f};
    #pragma unroll
    for (int mt = 0; mt < 2; mt++) {
        #pragma unroll
        for (int np = 0; np < 4; np++) {
            #pragma unroll
            for (int h = 0; h < 2; h++) {
                const float* a4 = acc[mt][np * 2 + h];
                const int r0 = wm + mt * 16 + g;
                const int c0 = n0 + wnn + np * 16 + h * 8 + 2 * t4;
                const size_t o0 = ((size_t)b * P1c + p0 + r0) * P2c + c0;
                const size_t o1 = o0 + (size_t)8 * P2c;
                *(float2*)(g_E + o0) = make_float2(a4[0], a4[1]);
                *(float2*)(g_E + o1) = make_float2(a4[2], a4[3]);
                srow[mt*2+0] += __expf(a4[0]) + __expf(a4[1]);
                srow[mt*2+1] += __expf(a4[2]) + __expf(a4[3]);
            }
        }
    }
    // quad reduce (lanes in a quad share the same rows)
    #pragma unroll
    for (int i = 0; i < 4; i++) {
        srow[i] += __shfl_xor_sync(0xffffffffu, srow[i], 1);
        srow[i] += __shfl_xor_sync(0xffffffffu, srow[i], 2);
    }
    if (t4 == 0) {
        #pragma unroll
        for (int i = 0; i < 4; i++) {
            const int r = wm + (i >> 1) * 16 + g + (i & 1) * 8;
            atomicAdd(&s_sum[r], srow[i]);   // smem atomic: 4 n-warps combine
        }
    }
    __syncthreads();
    if (tid < 64)
        g_part[(((size_t)b * P1c + p0 + tid) << 4) + blockIdx.x] = s_sum[tid];
}

// ---------------------------------------------------------------------------
// K2r: reduce 16 partials per row -> iz = 1/sum
// ---------------------------------------------------------------------------
__global__ void __launch_bounds__(256) iz_reduce_kernel()
{
    const int row = blockIdx.x * 256 + threadIdx.x;   // 0 .. B*P1-1
    const float* p = g_part + ((size_t)row << 4);
    float s = 0.f;
    #pragma unroll
    for (int j = 0; j < 16; j++) s += p[j];
    g_iz[row] = 1.0f / s;
}

// ---------------------------------------------------------------------------
// K2b: W[b][p][q2] = fp16( exp(e) * iz[p] ).  Streaming pass.
// ---------------------------------------------------------------------------
__global__ void __launch_bounds__(256) norm_kernel()
{
    const size_t i = (((size_t)blockIdx.x * 256) + threadIdx.x) * 8;
    const float iz = g_iz[i >> 12];
    float4 a = *(const float4*)(g_E + i);
    float4 c = *(const float4*)(g_E + i + 4);
    __half2 h0 = __floats2half2_rn(__expf(a.x) * iz, __expf(a.y) * iz);
    __half2 h1 = __floats2half2_rn(__expf(a.z) * iz, __expf(a.w) * iz);
    __half2 h2 = __floats2half2_rn(__expf(c.x) * iz, __expf(c.y) * iz);
    __half2 h3 = __floats2half2_rn(__expf(c.z) * iz, __expf(c.w) * iz);
    uint4 u;
    u.x = *(uint32_t*)&h0; u.y = *(uint32_t*)&h1;
    u.z = *(uint32_t*)&h2; u.w = *(uint32_t*)&h3;
    *(uint4*)(g_W + i) = u;
}

// ---------------------------------------------------------------------------
// K3: fp16 mma.sync m16n8k16 GEMM, 4-stage cp.async pipeline (unchanged from
// the passing round-9 kernel).
// ---------------------------------------------------------------------------
#define BK3 32
#define NCH (P1c / BK3)
#define NST 4
#define STAGE_BYTES 16384

__device__ __forceinline__ void cp16(uint32_t dst, const void* src) {
    asm volatile("cp.async.cg.shared.global [%0], [%1], 16;"
                 :: "r"(dst), "l"(src) : "memory");
}
__device__ __forceinline__ void cp_commit() {
    asm volatile("cp.async.commit_group;" ::: "memory");
}
__device__ __forceinline__ void cp_wait2() {
    asm volatile("cp.async.wait_group 2;" ::: "memory");
}

__global__ void __launch_bounds__(256, 2) out_gemm_h(
    const float* __restrict__ x2, const float* __restrict__ alpha,
    float* __restrict__ out)
{
    extern __shared__ __align__(16) uint8_t smem[];   // NST * 16KB

    const int b  = blockIdx.z;
    const int m0 = blockIdx.y * 128;
    const int n0 = blockIdx.x * 128;
    const int tid  = threadIdx.x;
    const int wid  = tid >> 5;
    const int lane = tid & 31;
    const int wm = (wid >> 1) * 32;
    const int wn = (wid & 1) * 64;

    const __half* Abase = g_vh + ((size_t)b * Cc  + m0) * (size_t)P1c;
    const __half* Wb    = g_W  + (size_t)b * P1c * P2c + n0;

    const int aRow0 = tid >> 2, aC16 = tid & 3;
    const int aS = aC16 >> 1, aC = aC16 & 1;
    const int bKt0 = tid >> 4, bNch = tid & 15;

    float acc[2][8][4];
    #pragma unroll
    for (int mt = 0; mt < 2; mt++)
        #pragma unroll
        for (int nt = 0; nt < 8; nt++)
            #pragma unroll
            for (int j = 0; j < 4; j++) acc[mt][nt][j] = 0.f;

    auto issue = [&](int ch) {
        uint8_t* st = smem + (ch & (NST - 1)) * STAGE_BYTES;
        const int k0 = ch * BK3;
        #pragma unroll
        for (int j = 0; j < 2; j++) {
            const int row = aRow0 + j * 64;
            cp16(su(st + aS * 4096 + row * 32 + ((aC ^ ((row >> 2) & 1)) << 4)),
                 Abase + (size_t)row * P1c + k0 + aC16 * 8);
        }
        #pragma unroll
        for (int j = 0; j < 2; j++) {
            const int kkt = bKt0 + j * 16;
            const int s = kkt >> 4, kk = kkt & 15;
            cp16(su(st + 8192 + s * 4096 + kk * 256 + ((bNch ^ (kk & 7)) << 4)),
                 Wb + (size_t)(k0 + kkt) * P2c + bNch * 8);
        }
    };

    #pragma unroll
    for (int c = 0; c < NST - 1; c++) {
        issue(c);
        cp_commit();
    }

    for (int ch = 0; ch < NCH; ch++) {
        cp_wait2();
        __syncthreads();

        const uint8_t* base = smem + (ch & (NST - 1)) * STAGE_BYTES;
        #pragma unroll
        for (int s = 0; s < 2; s++) {
            uint32_t a[2][4];
            #pragma unroll
            for (int mt = 0; mt < 2; mt++) {
                const int mr = wm + mt * 16 + (lane & 7) + ((lane >> 3) & 1) * 8;
                const int clog = (lane >> 4) & 1;
                ldsm_x4(a[mt], su(base + s * 4096 + mr * 32 +
                                  ((clog ^ ((mr >> 2) & 1)) << 4)));
            }
            const int kk = (lane & 7) + ((lane >> 3) & 1) * 8;
            #pragma unroll
            for (int np = 0; np < 4; np++) {
                const int nch = (wn + np * 16 + ((lane >> 4) & 1) * 8) >> 3;
                uint32_t br[4];
                ldsm_x4_t(br, su(base + 8192 + s * 4096 + kk * 256 +
                                 ((nch ^ (kk & 7)) << 4)));
                mma16816(acc[0][np * 2],     a[0], br[0], br[1]);
                mma16816(acc[1][np * 2],     a[1], br[0], br[1]);
                mma16816(acc[0][np * 2 + 1], a[0], br[2], br[3]);
                mma16816(acc[1][np * 2 + 1], a[1], br[2], br[3]);
            }
        }

        if (ch + NST - 1 < NCH) issue(ch + NST - 1);
        cp_commit();
    }

    const float al = __ldg(alpha);
    const int g  = lane >> 2;
    const int t4 = lane & 3;
    #pragma unroll
    for (int mt = 0; mt < 2; mt++) {
        #pragma unroll
        for (int nt = 0; nt < 8; nt++) {
            const int r0 = m0 + wm + mt * 16 + g;
            const int c0 = n0 + wn + nt * 8 + 2 * t4;
            const size_t o0 = ((size_t)b * Cc + r0) * P2c + c0;
            const size_t o1 = o0 + (size_t)8 * P2c;
            float2 x0 = *(const float2*)(x2 + o0);
            float2 x1 = *(const float2*)(x2 + o1);
            float2 w0, w1;
            w0.x = fmaf(al, acc[mt][nt][0], x0.x);
            w0.y = fmaf(al, acc[mt][nt][1], x0.y);
            w1.x = fmaf(al, acc[mt][nt][2], x1.x);
            w1.y = fmaf(al, acc[mt][nt][3], x1.y);
            *(float2*)(out + o0) = w0;
            *(float2*)(out + o1) = w1;
        }
    }
}

// ---------------------------------------------------------------------------
extern "C" void kernel_launch(void* const* d_in, const int* in_sizes, int n_in,
                              void* d_out, int out_size)
{
    (void)in_sizes; (void)n_in; (void)out_size;
    const float* x1    = (const float*)d_in[0];
    const float* x2    = (const float*)d_in[1];
    const float* Wq    = (const float*)d_in[2];
    const float* bq    = (const float*)d_in[3];
    const float* Wk    = (const float*)d_in[4];
    const float* bk    = (const float*)d_in[5];
    const float* Wv    = (const float*)d_in[6];
    const float* bv    = (const float*)d_in[7];
    const float* alpha = (const float*)d_in[8];
    float* out = (float*)d_out;

    void *pqh = nullptr, *pql = nullptr, *pkh = nullptr, *pkl = nullptr, *pv = nullptr;
    cudaGetSymbolAddress(&pqh, g_qh);
    cudaGetSymbolAddress(&pql, g_ql);
    cudaGetSymbolAddress(&pkh, g_kh);
    cudaGetSymbolAddress(&pkl, g_kl);
    cudaGetSymbolAddress(&pv,  g_vh);

    cudaFuncSetAttribute(out_gemm_h,
                         cudaFuncAttributeMaxDynamicSharedMemorySize,
                         NST * STAGE_BYTES);

    conv_qk_split_kernel<<<dim3(P1c / 256, 1, Bb), 256>>>(
        Wq, bq, x1, (__half*)pqh, (__half*)pql, P1c, 1);
    conv_qk_split_kernel<<<dim3(P2c / 256, 1, Bb), 256>>>(
        Wk, bk, x2, (__half*)pkh, (__half*)pkl, P2c, 0);
    conv1x1_h_kernel<<<dim3(P1c / 256, Cc / 32, Bb), 256>>>(
        Wv, bv, x1, (__half*)pv, P1c);

    energy_mma_kernel<<<dim3(P2c / 256, P1c / 64, Bb), 256>>>();

    iz_reduce_kernel<<<(Bb * P1c) / 256, 256>>>();

    norm_kernel<<<((size_t)Bb * P1c * P2c) / (256 * 8), 256>>>();

    out_gemm_h<<<dim3(P2c / 128, Cc / 128, Bb), 256, NST * STAGE_BYTES>>>(x2, alpha, out);
}